// round 14
// baseline (speedup 1.0000x reference)
#include <cuda_runtime.h>
#include <cuda_fp16.h>
#include <math.h>
#include <stdint.h>

// Problem constants (fixed shapes)
#define TSEQ 8192
#define MD   2048           // model dim
#define NH   64             // heads
#define NSD  32             // per-head state dim
#define PAIRS 1024          // NH * NSD/2
#define CH   64             // scan chunk length
#define NC   128            // number of chunks (TSEQ / CH)

#define KC     64           // K per chunk (fp16 -> 128 bytes/row)
#define NCHUNK (MD / KC)    // 32
#define CTA_M  128
#define CTA_N  256
#define NTHREADS 256        // 8 warps (2x4), warp tile 64x64

#define WSCALE     1024.0f
#define WSCALE_INV 0.0009765625f

// ---------------- scratch (static device globals; no allocation) -------------
__device__ float  g_P[NH*NSD*NSD];
__device__ float  g_xi[NH];
__device__ float  g_X[TSEQ*MD];
__device__ float2 g_carry[PAIRS*NC];
__device__ float2 g_carryExc[PAIRS*NC];

// fp16 operand buffers (weights stored pre-scaled by WSCALE)
__device__ __align__(256) __half g_Ah[TSEQ*MD];   // activations (input u, then hidden H)
__device__ __align__(256) __half g_W1h[MD*MD];
__device__ __align__(256) __half g_Ch[MD*MD];

// ================= PTX helpers (sm_80-class only) =============================
__device__ __forceinline__ uint32_t smem_u32(const void* p) {
    uint32_t a;
    asm("{ .reg .u64 t; cvta.to.shared.u64 t, %1; cvt.u32.u64 %0, t; }" : "=r"(a) : "l"(p));
    return a;
}
// SW128 swizzle for 128B rows
__device__ __forceinline__ uint32_t sw128(uint32_t b) { return b ^ ((b >> 3) & 0x70); }

__device__ __forceinline__ void cp16(uint32_t dst, const void* src) {
    asm volatile("cp.async.cg.shared.global [%0], [%1], 16;" :: "r"(dst), "l"(src) : "memory");
}
__device__ __forceinline__ void cp_commit() { asm volatile("cp.async.commit_group;" ::: "memory"); }
__device__ __forceinline__ void cp_wait1()  { asm volatile("cp.async.wait_group 1;"  ::: "memory"); }
__device__ __forceinline__ void cp_wait0()  { asm volatile("cp.async.wait_group 0;"  ::: "memory"); }

__device__ __forceinline__ void ldsm4(uint32_t addr, uint32_t& r0, uint32_t& r1,
                                      uint32_t& r2, uint32_t& r3) {
    asm volatile("ldmatrix.sync.aligned.m8n8.x4.shared.b16 {%0,%1,%2,%3}, [%4];"
                 : "=r"(r0), "=r"(r1), "=r"(r2), "=r"(r3) : "r"(addr));
}
__device__ __forceinline__ void mma_f16(float* d, uint32_t a0, uint32_t a1,
                                        uint32_t a2, uint32_t a3,
                                        uint32_t b0, uint32_t b1) {
    asm volatile("mma.sync.aligned.m16n8k16.row.col.f32.f16.f16.f32 "
                 "{%0,%1,%2,%3},{%4,%5,%6,%7},{%8,%9},{%0,%1,%2,%3};"
                 : "+f"(d[0]), "+f"(d[1]), "+f"(d[2]), "+f"(d[3])
                 : "r"(a0), "r"(a1), "r"(a2), "r"(a3), "r"(b0), "r"(b1));
}

// ---------------- per-head prep: btb trace, gamma, xi, P = expm(M - M^T) -----
__global__ void __launch_bounds__(1024)
prep_head_kernel(const float* __restrict__ M,
                 const float* __restrict__ B,
                 const float* __restrict__ gamma_log)
{
    const int h   = blockIdx.x;
    const int tid = threadIdx.x;
    const int r   = tid >> 5;
    const int c   = tid & 31;

    __shared__ float sA[32][33];
    __shared__ float sT[32][33];
    __shared__ float sS[32][33];
    __shared__ float sRed[32];
    __shared__ float sBtb;
    __shared__ int   sScale;

    const float* Bh = B + (size_t)h * NSD * MD;
    float lsum = 0.f;
    for (int e = tid; e < NSD*MD; e += 1024) { float v = Bh[e]; lsum += v*v; }
    #pragma unroll
    for (int o = 16; o; o >>= 1) lsum += __shfl_down_sync(0xffffffffu, lsum, o);
    if (c == 0) sRed[r] = lsum;

    sA[r][c] = M[(size_t)h*1024 + r*32 + c] - M[(size_t)h*1024 + c*32 + r];
    __syncthreads();

    if (tid == 0) {
        float s = 0.f;
        #pragma unroll
        for (int w = 0; w < 32; w++) s += sRed[w];
        sBtb = s;
    }

    float av = fabsf(sA[r][c]);
    #pragma unroll
    for (int o = 16; o; o >>= 1) av += __shfl_down_sync(0xffffffffu, av, o);
    __syncthreads();
    if (c == 0) sRed[r] = av;
    __syncthreads();
    if (tid == 0) {
        float mx = 0.f;
        #pragma unroll
        for (int w = 0; w < 32; w++) mx = fmaxf(mx, sRed[w]);
        int s = 0;
        while (mx > 0.5f && s < 40) { mx *= 0.5f; s++; }
        sScale = s;
    }
    __syncthreads();

    const int s = sScale;
    const float sc = ldexpf(1.0f, -s);
    float a = sA[r][c] * sc;
    sA[r][c] = a;
    sT[r][c] = a;
    sS[r][c] = a + (r == c ? 1.0f : 0.0f);
    __syncthreads();

    for (int j = 2; j <= 14; j++) {
        float acc = 0.f;
        #pragma unroll
        for (int k = 0; k < 32; k++) acc += sT[r][k] * sA[k][c];
        acc *= (1.0f / (float)j);
        __syncthreads();
        sT[r][c] = acc;
        sS[r][c] += acc;
        __syncthreads();
    }
    for (int it = 0; it < s; it++) {
        float acc = 0.f;
        #pragma unroll
        for (int k = 0; k < 32; k++) acc += sS[r][k] * sS[k][c];
        __syncthreads();
        sS[r][c] = acc;
        __syncthreads();
    }
    g_P[(size_t)h*1024 + r*32 + c] = sS[r][c];

    if (tid == 0) {
        float e  = expf(gamma_log[h]);
        float gm = expf(-e);
        g_xi[h]  = sqrtf((1.0f - gm*gm) / sBtb);
    }
}

// ---- W1[h*32+n][i] = xi_h * sum_m P[h,m,n] * B[h,m,i]; write scaled fp16 -----
__global__ void __launch_bounds__(256)
beff_split_kernel(const float* __restrict__ B)
{
    const int h  = blockIdx.y;
    const int i0 = blockIdx.x * 256;
    const int tid = threadIdx.x;

    __shared__ float Ps[32][32];
    __shared__ float Bs[32][256];

    for (int e = tid; e < 1024; e += 256) Ps[e >> 5][e & 31] = g_P[(size_t)h*1024 + e];
    for (int e = tid; e < 32*256; e += 256) {
        int m = e >> 8, i = e & 255;
        Bs[m][i] = B[(size_t)h*NSD*MD + (size_t)m*MD + i0 + i];
    }
    __syncthreads();

    const float xi = g_xi[h];
    const int i = tid;
    #pragma unroll 4
    for (int n = 0; n < 32; n++) {
        float acc = 0.f;
        #pragma unroll
        for (int m = 0; m < 32; m++) acc += Ps[m][n] * Bs[m][i];
        g_W1h[(size_t)(h*32 + n) * MD + i0 + i] = __float2half_rn(xi * acc * WSCALE);
    }
}

// ---- Ceff[d][h*32+i] = sum_n C[d][h*32+n] * P[h,n,i]; write scaled fp16 ------
__global__ void __launch_bounds__(256)
ceff_split_kernel(const float* __restrict__ C)
{
    const int h = blockIdx.y;
    const int d = blockIdx.x * 256 + threadIdx.x;
    const int tid = threadIdx.x;

    __shared__ float Ps[32][32];
    for (int e = tid; e < 1024; e += 256) Ps[e >> 5][e & 31] = g_P[(size_t)h*1024 + e];
    __syncthreads();

    float cr[32];
    const float* Crow = C + (size_t)d * MD + h * 32;
    #pragma unroll
    for (int n = 0; n < 32; n++) cr[n] = Crow[n];

    #pragma unroll 4
    for (int i = 0; i < 32; i++) {
        float acc = 0.f;
        #pragma unroll
        for (int n = 0; n < 32; n++) acc += cr[n] * Ps[n][i];
        g_Ch[(size_t)d * MD + h * 32 + i] = __float2half_rn(acc * WSCALE);
    }
}

// ---------------- fp32 -> fp16 convert (activations) -------------------------
__global__ void __launch_bounds__(256)
conv_half_kernel(const float* __restrict__ src, __half* __restrict__ dst, int n4)
{
    int i = blockIdx.x * 256 + threadIdx.x;
    if (i >= n4) return;
    float4 v = ((const float4*)src)[i];
    __half2 h0 = __floats2half2_rn(v.x, v.y);
    __half2 h1 = __floats2half2_rn(v.z, v.w);
    uint2 o;
    o.x = *(uint32_t*)&h0; o.y = *(uint32_t*)&h1;
    ((uint2*)dst)[i] = o;
}

// ---------------- mma.sync GEMM: Out[m][n] = sum_k A[m][k]*W[n][k] (+ D*U) ----
// Pure fp16 1-term: Ah*Wh (W pre-scaled by WSCALE, epilogue unscales).
// CTA tile 128x256, 256 threads (8 warps, 2x4), warp tile 64x64.
// K-chunk 64 (SW128), 3-stage cp.async pipeline, 1 CTA/SM (2 warps/SMSP).
// One barrier per chunk; hoisted global/smem addressing.
#define OFF_A  0
#define OFF_W  16384
#define STAGE_BYTES 49152       // A 16KB + W 32KB
#define NSTAGE 3
#define GEMM_SMEM (NSTAGE*STAGE_BYTES)   // 147456

template <int MODE>
__global__ void __launch_bounds__(NTHREADS, 1)
mma_gemm_kernel(const __half* __restrict__ Ah,
                const __half* __restrict__ Wh,
                const float* __restrict__ in0,
                const float* __restrict__ Dv,
                float* __restrict__ Cout)
{
    extern __shared__ __align__(1024) char smem[];
    const uint32_t sb = smem_u32(smem);
    const int tid  = threadIdx.x;
    const int lane = tid & 31;
    const int wid  = tid >> 5;
    const int wr   = wid >> 2;          // 0..1 (M half, 64 rows)
    const int wc   = wid & 3;           // 0..3 (N quarter, 64 cols)
    const int m0   = blockIdx.y * CTA_M;
    const int n0   = blockIdx.x * CTA_N;

    const int jj   = lane >> 3;                 // ldmatrix matrix index 0..3
    const int lrow = (jj & 1) * 8 + (lane & 7); // row within 16-row frag
    const int lkb  = (jj >> 1) * 16;            // k-byte offset (0 or 16)

    // per-warp base smem offsets for fragment loads (kstep adds kb)
    const uint32_t wbase = (uint32_t)((wc * 64 + lrow) * 128 + lkb);
    const uint32_t abase = (uint32_t)((wr * 64 + lrow) * 128 + lkb);

    // ---- hoisted cp.async addressing: seg fixed per thread, rows step by 32
    const int rb  = tid >> 3;                   // base row 0..31
    const int seg = tid & 7;
    const uint32_t so = sw128((uint32_t)(rb * 128 + seg * 16));  // +j*4096 per row step
    const __half* gA = Ah + (size_t)(m0 + rb) * MD + seg * 8;    // advance by KC per chunk
    const __half* gW = Wh + (size_t)(n0 + rb) * MD + seg * 8;

    auto load_chunk = [&](const __half* pA, const __half* pW, int s) {
        const uint32_t base = sb + s * STAGE_BYTES;
        #pragma unroll
        for (int j = 0; j < 4; j++)             // A: 128 rows (32-row steps)
            cp16(base + OFF_A + so + j * 4096, pA + (size_t)j * 32 * MD);
        #pragma unroll
        for (int j = 0; j < 8; j++)             // W: 256 rows (32-row steps)
            cp16(base + OFF_W + so + j * 4096, pW + (size_t)j * 32 * MD);
        cp_commit();
    };

    float acc[4][8][4];
    #pragma unroll
    for (int i = 0; i < 4; i++)
        #pragma unroll
        for (int j = 0; j < 8; j++)
            #pragma unroll
            for (int k = 0; k < 4; k++) acc[i][j][k] = 0.f;

    load_chunk(gA, gW, 0);
    load_chunk(gA + KC, gW + KC, 1);
    const __half* pA2 = gA + 2 * KC;     // next chunk to load
    const __half* pW2 = gW + 2 * KC;

    for (int c = 0; c < NCHUNK; c++) {
        if (c + 1 < NCHUNK) cp_wait1(); else cp_wait0();
        __syncthreads();
        // Stage (c+2)%3 was last READ during chunk c-1; all warps passed the
        // barrier after finishing c-1, so overwriting it now is safe.
        if (c + 2 < NCHUNK) {
            load_chunk(pA2, pW2, (c + 2) % NSTAGE);
            pA2 += KC; pW2 += KC;
        }

        const uint32_t base = sb + (c % NSTAGE) * STAGE_BYTES;
        #pragma unroll
        for (int ks = 0; ks < 4; ks++) {
            const int kb = ks * 32;

            uint32_t w[16];
            #pragma unroll
            for (int g_ = 0; g_ < 4; g_++) {
                uint32_t offw = sw128(wbase + g_ * 16 * 128 + (uint32_t)kb);
                ldsm4(base + OFF_W + offw, w[g_*4+0], w[g_*4+1], w[g_*4+2], w[g_*4+3]);
            }

            #pragma unroll
            for (int i = 0; i < 4; i++) {
                uint32_t offa = sw128(abase + i * 16 * 128 + (uint32_t)kb);
                uint32_t a0, a1, a2, a3;
                ldsm4(base + OFF_A + offa, a0, a1, a2, a3);
                #pragma unroll
                for (int j = 0; j < 8; j++) {
                    uint32_t b0 = w[(j >> 1) * 4 + (j & 1)];
                    uint32_t b1 = w[(j >> 1) * 4 + (j & 1) + 2];
                    mma_f16(acc[i][j], a0, a1, a2, a3, b0, b1);
                }
            }
        }
    }

    // ---- epilogue: unscale, optional D*U, store ----
    const int g = lane >> 2, t = lane & 3;
    #pragma unroll
    for (int i = 0; i < 4; i++) {
        const int mrow = m0 + wr * 64 + i * 16 + g;
        #pragma unroll
        for (int j = 0; j < 8; j++) {
            const int n = n0 + wc * 64 + j * 8 + 2 * t;
            float2 v0 = make_float2(acc[i][j][0] * WSCALE_INV, acc[i][j][1] * WSCALE_INV);
            float2 v1 = make_float2(acc[i][j][2] * WSCALE_INV, acc[i][j][3] * WSCALE_INV);
            if (MODE == 1) {
                float2 dp = *(const float2*)(Dv + n);
                float2 u0 = *(const float2*)(in0 + (size_t)mrow * MD + n);
                float2 u1 = *(const float2*)(in0 + (size_t)(mrow + 8) * MD + n);
                v0.x = fmaf(dp.x, u0.x, v0.x); v0.y = fmaf(dp.y, u0.y, v0.y);
                v1.x = fmaf(dp.x, u1.x, v1.x); v1.y = fmaf(dp.y, u1.y, v1.y);
            }
            *(float2*)(Cout + (size_t)mrow * MD + n)       = v0;
            *(float2*)(Cout + (size_t)(mrow + 8) * MD + n) = v1;
        }
    }
}

// ------- scan phase 1 (read-only): chunk-local scan -> carry only -------------
__global__ void __launch_bounds__(256)
scan_local_kernel(const float* __restrict__ gamma_log,
                  const float* __restrict__ thetas)
{
    const int p = blockIdx.x * 256 + threadIdx.x;
    const int c = blockIdx.y;
    const int h = p >> 4, q = p & 15;

    const float e  = expf(gamma_log[h]);
    const float g  = expf(-e);
    const float th = thetas[(h << 4) + q];
    const float gc = g * cosf(th);
    const float gs = g * sinf(th);

    float a0 = 0.f, a1 = 0.f;
    const float2* Xp = (const float2*)g_X;
    const int base = c * CH;
    #pragma unroll 4
    for (int i = 0; i < CH; i++) {
        const size_t idx = (size_t)(base + i) * (MD/2) + p;
        float2 x = Xp[idx];
        float b0 = gc*a0 - gs*a1 + x.x;
        float b1 = gs*a0 + gc*a1 + x.y;
        a0 = b0; a1 = b1;
    }
    g_carry[p*NC + c] = make_float2(a0, a1);
}

// ---------------- scan phase 2: exclusive scan of chunk carries ---------------
__global__ void __launch_bounds__(256)
scan_carry_kernel(const float* __restrict__ gamma_log,
                  const float* __restrict__ thetas)
{
    const int p = blockIdx.x * 256 + threadIdx.x;
    const int h = p >> 4, q = p & 15;

    const float e   = expf(gamma_log[h]);
    const float gC  = expf(-(float)CH * e);
    const float thC = thetas[(h << 4) + q] * (float)CH;
    const float cs  = cosf(thC), sn = sinf(thC);

    float a0 = 0.f, a1 = 0.f;
    for (int c = 0; c < NC; c++) {
        g_carryExc[p*NC + c] = make_float2(a0, a1);
        float2 l = g_carry[p*NC + c];
        float b0 = gC*(cs*a0 - sn*a1) + l.x;
        float b1 = gC*(sn*a0 + cs*a1) + l.y;
        a0 = b0; a1 = b1;
    }
}

// --- scan phase 3: recompute local scan seeded with carry; write fp16 hidden --
__global__ void __launch_bounds__(256)
scan_apply_half_kernel(const float* __restrict__ gamma_log,
                       const float* __restrict__ thetas,
                       __half* __restrict__ Hh)
{
    const int p = blockIdx.x * 256 + threadIdx.x;
    const int c = blockIdx.y;

    const int h = p >> 4, q = p & 15;
    const float e  = expf(gamma_log[h]);
    const float g  = expf(-e);
    const float th = thetas[(h << 4) + q];
    const float gc = g * cosf(th);
    const float gs = g * sinf(th);

    float2 v = g_carryExc[p*NC + c];     // incoming prefix ((0,0) for c==0)
    float v0 = v.x, v1 = v.y;
    const float2* Xp = (const float2*)g_X;
    __half2* Hp = (__half2*)Hh;
    const int base = c * CH;
    #pragma unroll 4
    for (int i = 0; i < CH; i++) {
        const size_t idx = (size_t)(base + i) * (MD/2) + p;
        float2 x = Xp[idx];
        float b0 = gc*v0 - gs*v1 + x.x;
        float b1 = gs*v0 + gc*v1 + x.y;
        v0 = b0; v1 = b1;
        Hp[idx] = __floats2half2_rn(v0, v1);
    }
}

// ---------------- launch ------------------------------------------------------
extern "C" void kernel_launch(void* const* d_in, const int* in_sizes, int n_in,
                              void* d_out, int out_size)
{
    const float* in_seq    = (const float*)d_in[0];   // (8192, 2048)
    const float* thetas    = (const float*)d_in[1];   // (64, 16)
    const float* Mmat      = (const float*)d_in[2];   // (64, 32, 32)
    const float* Bmat      = (const float*)d_in[3];   // (64, 32, 2048)
    const float* Cmat      = (const float*)d_in[4];   // (2048, 2048)
    const float* Dvec      = (const float*)d_in[5];   // (2048,)
    const float* gamma_log = (const float*)d_in[6];   // (64, 1)
    float* out = (float*)d_out;                       // (8192, 2048)

    cudaFuncSetAttribute(mma_gemm_kernel<0>, cudaFuncAttributeMaxDynamicSharedMemorySize, GEMM_SMEM);
    cudaFuncSetAttribute(mma_gemm_kernel<1>, cudaFuncAttributeMaxDynamicSharedMemorySize, GEMM_SMEM);

    float *pX;
    __half *pAh, *pW1h, *pCh;
    cudaGetSymbolAddress((void**)&pX,   g_X);
    cudaGetSymbolAddress((void**)&pAh,  g_Ah);
    cudaGetSymbolAddress((void**)&pW1h, g_W1h);
    cudaGetSymbolAddress((void**)&pCh,  g_Ch);

    // Launch order: the 4th launch is the one ncu captures -> GEMM0.
    prep_head_kernel<<<NH, 1024>>>(Mmat, Bmat, gamma_log);                          // 1
    beff_split_kernel<<<dim3(MD/256, NH), 256>>>(Bmat);                             // 2
    conv_half_kernel<<<(TSEQ*MD/4 + 255)/256, 256>>>(in_seq, pAh, TSEQ*MD/4);       // 3

    // GEMM0: X = U * W1^T                                                          // 4 (profiled)
    mma_gemm_kernel<0><<<dim3(MD/CTA_N, TSEQ/CTA_M), NTHREADS, GEMM_SMEM>>>(
        pAh, pW1h, nullptr, nullptr, pX);

    ceff_split_kernel<<<dim3(MD/256, NH), 256>>>(Cmat);                             // 5

    // scan: phase1 read-only carries, phase2 carry scan, phase3 recompute+fp16
    scan_local_kernel<<<dim3(PAIRS/256, NC), 256>>>(gamma_log, thetas);             // 6
    scan_carry_kernel<<<PAIRS/256, 256>>>(gamma_log, thetas);                       // 7
    scan_apply_half_kernel<<<dim3(PAIRS/256, NC), 256>>>(gamma_log, thetas, pAh);   // 8

    // GEMM1: out = H * Ceff^T + D .* U
    mma_gemm_kernel<1><<<dim3(MD/CTA_N, TSEQ/CTA_M), NTHREADS, GEMM_SMEM>>>(
        pAh, pCh, in_seq, Dvec, out);                                               // 9
}

// round 15
// speedup vs baseline: 1.1943x; 1.1943x over previous
#include <cuda_runtime.h>
#include <cuda_fp16.h>
#include <math.h>
#include <stdint.h>

// Problem constants (fixed shapes)
#define TSEQ 8192
#define MD   2048           // model dim
#define NH   64             // heads
#define NSD  32             // per-head state dim
#define PAIRS 1024          // NH * NSD/2
#define CH   64             // scan chunk length
#define NC   128            // number of chunks (TSEQ / CH)

#define KC     64           // K per chunk (fp16 -> 128 bytes/row)
#define NCHUNK (MD / KC)    // 32
#define CTA_M  128
#define CTA_N  128
#define NTHREADS 128        // 4 warps, warp tile 64x64

#define WSCALE     1024.0f
#define WSCALE_INV 0.0009765625f

// ---------------- scratch (static device globals; no allocation) -------------
__device__ float  g_P[NH*NSD*NSD];
__device__ float  g_xi[NH];
__device__ float2 g_carry[PAIRS*NC];
__device__ float2 g_carryExc[PAIRS*NC];

// fp16 operand buffers (weights stored pre-scaled by WSCALE)
__device__ __align__(256) __half g_Ah[TSEQ*MD];   // activations (input u, then hidden H)
__device__ __align__(256) __half g_Xh[TSEQ*MD];   // GEMM0 output x (fp16)
__device__ __align__(256) __half g_W1h[MD*MD];
__device__ __align__(256) __half g_Ch[MD*MD];

// ================= PTX helpers (sm_80-class only) =============================
__device__ __forceinline__ uint32_t smem_u32(const void* p) {
    uint32_t a;
    asm("{ .reg .u64 t; cvta.to.shared.u64 t, %1; cvt.u32.u64 %0, t; }" : "=r"(a) : "l"(p));
    return a;
}
// SW128 swizzle for 128B rows
__device__ __forceinline__ uint32_t sw128(uint32_t b) { return b ^ ((b >> 3) & 0x70); }

__device__ __forceinline__ void cp16(uint32_t dst, const void* src) {
    asm volatile("cp.async.cg.shared.global [%0], [%1], 16;" :: "r"(dst), "l"(src) : "memory");
}
__device__ __forceinline__ void cp_commit() { asm volatile("cp.async.commit_group;" ::: "memory"); }
__device__ __forceinline__ void cp_wait1()  { asm volatile("cp.async.wait_group 1;"  ::: "memory"); }
__device__ __forceinline__ void cp_wait0()  { asm volatile("cp.async.wait_group 0;"  ::: "memory"); }

__device__ __forceinline__ void ldsm4(uint32_t addr, uint32_t& r0, uint32_t& r1,
                                      uint32_t& r2, uint32_t& r3) {
    asm volatile("ldmatrix.sync.aligned.m8n8.x4.shared.b16 {%0,%1,%2,%3}, [%4];"
                 : "=r"(r0), "=r"(r1), "=r"(r2), "=r"(r3) : "r"(addr));
}
__device__ __forceinline__ void mma_f16(float* d, uint32_t a0, uint32_t a1,
                                        uint32_t a2, uint32_t a3,
                                        uint32_t b0, uint32_t b1) {
    asm volatile("mma.sync.aligned.m16n8k16.row.col.f32.f16.f16.f32 "
                 "{%0,%1,%2,%3},{%4,%5,%6,%7},{%8,%9},{%0,%1,%2,%3};"
                 : "+f"(d[0]), "+f"(d[1]), "+f"(d[2]), "+f"(d[3])
                 : "r"(a0), "r"(a1), "r"(a2), "r"(a3), "r"(b0), "r"(b1));
}

// ---------------- per-head prep: btb trace, gamma, xi, P = expm(M - M^T) -----
__global__ void __launch_bounds__(1024)
prep_head_kernel(const float* __restrict__ M,
                 const float* __restrict__ B,
                 const float* __restrict__ gamma_log)
{
    const int h   = blockIdx.x;
    const int tid = threadIdx.x;
    const int r   = tid >> 5;
    const int c   = tid & 31;

    __shared__ float sA[32][33];
    __shared__ float sT[32][33];
    __shared__ float sS[32][33];
    __shared__ float sRed[32];
    __shared__ float sBtb;
    __shared__ int   sScale;

    const float* Bh = B + (size_t)h * NSD * MD;
    float lsum = 0.f;
    for (int e = tid; e < NSD*MD; e += 1024) { float v = Bh[e]; lsum += v*v; }
    #pragma unroll
    for (int o = 16; o; o >>= 1) lsum += __shfl_down_sync(0xffffffffu, lsum, o);
    if (c == 0) sRed[r] = lsum;

    sA[r][c] = M[(size_t)h*1024 + r*32 + c] - M[(size_t)h*1024 + c*32 + r];
    __syncthreads();

    if (tid == 0) {
        float s = 0.f;
        #pragma unroll
        for (int w = 0; w < 32; w++) s += sRed[w];
        sBtb = s;
    }

    float av = fabsf(sA[r][c]);
    #pragma unroll
    for (int o = 16; o; o >>= 1) av += __shfl_down_sync(0xffffffffu, av, o);
    __syncthreads();
    if (c == 0) sRed[r] = av;
    __syncthreads();
    if (tid == 0) {
        float mx = 0.f;
        #pragma unroll
        for (int w = 0; w < 32; w++) mx = fmaxf(mx, sRed[w]);
        int s = 0;
        while (mx > 0.5f && s < 40) { mx *= 0.5f; s++; }
        sScale = s;
    }
    __syncthreads();

    const int s = sScale;
    const float sc = ldexpf(1.0f, -s);
    float a = sA[r][c] * sc;
    sA[r][c] = a;
    sT[r][c] = a;
    sS[r][c] = a + (r == c ? 1.0f : 0.0f);
    __syncthreads();

    for (int j = 2; j <= 14; j++) {
        float acc = 0.f;
        #pragma unroll
        for (int k = 0; k < 32; k++) acc += sT[r][k] * sA[k][c];
        acc *= (1.0f / (float)j);
        __syncthreads();
        sT[r][c] = acc;
        sS[r][c] += acc;
        __syncthreads();
    }
    for (int it = 0; it < s; it++) {
        float acc = 0.f;
        #pragma unroll
        for (int k = 0; k < 32; k++) acc += sS[r][k] * sS[k][c];
        __syncthreads();
        sS[r][c] = acc;
        __syncthreads();
    }
    g_P[(size_t)h*1024 + r*32 + c] = sS[r][c];

    if (tid == 0) {
        float e  = expf(gamma_log[h]);
        float gm = expf(-e);
        g_xi[h]  = sqrtf((1.0f - gm*gm) / sBtb);
    }
}

// ---- W1[h*32+n][i] = xi_h * sum_m P[h,m,n] * B[h,m,i]; write scaled fp16 -----
__global__ void __launch_bounds__(256)
beff_split_kernel(const float* __restrict__ B)
{
    const int h  = blockIdx.y;
    const int i0 = blockIdx.x * 256;
    const int tid = threadIdx.x;

    __shared__ float Ps[32][32];
    __shared__ float Bs[32][256];

    for (int e = tid; e < 1024; e += 256) Ps[e >> 5][e & 31] = g_P[(size_t)h*1024 + e];
    for (int e = tid; e < 32*256; e += 256) {
        int m = e >> 8, i = e & 255;
        Bs[m][i] = B[(size_t)h*NSD*MD + (size_t)m*MD + i0 + i];
    }
    __syncthreads();

    const float xi = g_xi[h];
    const int i = tid;
    #pragma unroll 4
    for (int n = 0; n < 32; n++) {
        float acc = 0.f;
        #pragma unroll
        for (int m = 0; m < 32; m++) acc += Ps[m][n] * Bs[m][i];
        g_W1h[(size_t)(h*32 + n) * MD + i0 + i] = __float2half_rn(xi * acc * WSCALE);
    }
}

// ---- Ceff[d][h*32+i] = sum_n C[d][h*32+n] * P[h,n,i]; write scaled fp16 ------
__global__ void __launch_bounds__(256)
ceff_split_kernel(const float* __restrict__ C)
{
    const int h = blockIdx.y;
    const int d = blockIdx.x * 256 + threadIdx.x;
    const int tid = threadIdx.x;

    __shared__ float Ps[32][32];
    for (int e = tid; e < 1024; e += 256) Ps[e >> 5][e & 31] = g_P[(size_t)h*1024 + e];
    __syncthreads();

    float cr[32];
    const float* Crow = C + (size_t)d * MD + h * 32;
    #pragma unroll
    for (int n = 0; n < 32; n++) cr[n] = Crow[n];

    #pragma unroll 4
    for (int i = 0; i < 32; i++) {
        float acc = 0.f;
        #pragma unroll
        for (int n = 0; n < 32; n++) acc += cr[n] * Ps[n][i];
        g_Ch[(size_t)d * MD + h * 32 + i] = __float2half_rn(acc * WSCALE);
    }
}

// ---------------- fp32 -> fp16 convert (activations) -------------------------
__global__ void __launch_bounds__(256)
conv_half_kernel(const float* __restrict__ src, __half* __restrict__ dst, int n4)
{
    int i = blockIdx.x * 256 + threadIdx.x;
    if (i >= n4) return;
    float4 v = ((const float4*)src)[i];
    __half2 h0 = __floats2half2_rn(v.x, v.y);
    __half2 h1 = __floats2half2_rn(v.z, v.w);
    uint2 o;
    o.x = *(uint32_t*)&h0; o.y = *(uint32_t*)&h1;
    ((uint2*)dst)[i] = o;
}

// ---------------- mma.sync GEMM: Out[m][n] = sum_k A[m][k]*W[n][k] (+ D*U) ----
// Pure fp16 1-term: Ah*Wh (W pre-scaled by WSCALE, epilogue unscales).
// CTA tile 128x128, 128 threads (4 warps), warp tile 64x64.
// K-chunk 64 (SW128), 3-stage cp.async pipeline, 2 CTAs/SM.
// MODE 0: store fp16 to CoutH (scan input).  MODE 1: fp32 out + D*U epilogue.
#define OFF_A  0
#define OFF_W  16384
#define STAGE_BYTES 32768
#define NSTAGE 3
#define GEMM_SMEM (NSTAGE*STAGE_BYTES)   // 98304

template <int MODE>
__global__ void __launch_bounds__(NTHREADS, 2)
mma_gemm_kernel(const __half* __restrict__ Ah,
                const __half* __restrict__ Wh,
                const float* __restrict__ in0,
                const float* __restrict__ Dv,
                float* __restrict__ Cout,
                __half* __restrict__ CoutH)
{
    extern __shared__ __align__(1024) char smem[];
    const uint32_t sb = smem_u32(smem);
    const int tid  = threadIdx.x;
    const int lane = tid & 31;
    const int wid  = tid >> 5;
    const int wr   = wid >> 1;          // 0..1 (M half, 64 rows)
    const int wc   = wid & 1;           // 0..1 (N half, 64 cols)
    const int m0   = blockIdx.y * CTA_M;
    const int n0   = blockIdx.x * CTA_N;

    const int jj   = lane >> 3;                 // ldmatrix matrix index 0..3
    const int lrow = (jj & 1) * 8 + (lane & 7); // row within 16-row frag
    const int lkb  = (jj >> 1) * 16;            // k-byte offset (0 or 16)

    // per-warp base smem offsets for fragment loads (kstep adds kb)
    const uint32_t wbase = (uint32_t)((wc * 64 + lrow) * 128 + lkb);
    const uint32_t abase = (uint32_t)((wr * 64 + lrow) * 128 + lkb);

    // ---- hoisted cp.async addressing: seg fixed per thread, rows step by 16
    const int rb  = tid >> 3;                   // base row 0..15
    const int seg = tid & 7;
    const uint32_t so = sw128((uint32_t)(rb * 128 + seg * 16));  // +j*2048 per row step
    const __half* gA = Ah + (size_t)(m0 + rb) * MD + seg * 8;    // advance by KC per chunk
    const __half* gW = Wh + (size_t)(n0 + rb) * MD + seg * 8;

    auto load_chunk = [&](const __half* pA, const __half* pW, int s) {
        const uint32_t base = sb + s * STAGE_BYTES;
        #pragma unroll
        for (int j = 0; j < 8; j++) {
            cp16(base + OFF_A + so + j * 2048, pA + (size_t)j * 16 * MD);
            cp16(base + OFF_W + so + j * 2048, pW + (size_t)j * 16 * MD);
        }
        cp_commit();
    };

    float acc[4][8][4];
    #pragma unroll
    for (int i = 0; i < 4; i++)
        #pragma unroll
        for (int j = 0; j < 8; j++)
            #pragma unroll
            for (int k = 0; k < 4; k++) acc[i][j][k] = 0.f;

    load_chunk(gA, gW, 0);
    load_chunk(gA + KC, gW + KC, 1);
    const __half* pA2 = gA + 2 * KC;     // next chunk to load
    const __half* pW2 = gW + 2 * KC;

    for (int c = 0; c < NCHUNK; c++) {
        if (c + 1 < NCHUNK) cp_wait1(); else cp_wait0();
        __syncthreads();
        // Stage (c+2)%3 was last READ during chunk c-1; all warps passed the
        // barrier after finishing c-1, so overwriting it now is safe.
        if (c + 2 < NCHUNK) {
            load_chunk(pA2, pW2, (c + 2) % NSTAGE);
            pA2 += KC; pW2 += KC;
        }

        const uint32_t base = sb + (c % NSTAGE) * STAGE_BYTES;
        #pragma unroll
        for (int ks = 0; ks < 4; ks++) {
            const int kb = ks * 32;

            uint32_t w[16];
            #pragma unroll
            for (int g_ = 0; g_ < 4; g_++) {
                uint32_t offw = sw128(wbase + g_ * 16 * 128 + (uint32_t)kb);
                ldsm4(base + OFF_W + offw, w[g_*4+0], w[g_*4+1], w[g_*4+2], w[g_*4+3]);
            }

            #pragma unroll
            for (int i = 0; i < 4; i++) {
                uint32_t offa = sw128(abase + i * 16 * 128 + (uint32_t)kb);
                uint32_t a0, a1, a2, a3;
                ldsm4(base + OFF_A + offa, a0, a1, a2, a3);
                #pragma unroll
                for (int j = 0; j < 8; j++) {
                    uint32_t b0 = w[(j >> 1) * 4 + (j & 1)];
                    uint32_t b1 = w[(j >> 1) * 4 + (j & 1) + 2];
                    mma_f16(acc[i][j], a0, a1, a2, a3, b0, b1);
                }
            }
        }
    }

    // ---- epilogue: unscale; MODE 0 -> fp16 store, MODE 1 -> fp32 + D*U ----
    const int g = lane >> 2, t = lane & 3;
    #pragma unroll
    for (int i = 0; i < 4; i++) {
        const int mrow = m0 + wr * 64 + i * 16 + g;
        #pragma unroll
        for (int j = 0; j < 8; j++) {
            const int n = n0 + wc * 64 + j * 8 + 2 * t;
            float2 v0 = make_float2(acc[i][j][0] * WSCALE_INV, acc[i][j][1] * WSCALE_INV);
            float2 v1 = make_float2(acc[i][j][2] * WSCALE_INV, acc[i][j][3] * WSCALE_INV);
            if (MODE == 0) {
                __half2 h0 = __floats2half2_rn(v0.x, v0.y);
                __half2 h1 = __floats2half2_rn(v1.x, v1.y);
                *(__half2*)(CoutH + (size_t)mrow * MD + n)       = h0;
                *(__half2*)(CoutH + (size_t)(mrow + 8) * MD + n) = h1;
            } else {
                float2 dp = *(const float2*)(Dv + n);
                float2 u0 = *(const float2*)(in0 + (size_t)mrow * MD + n);
                float2 u1 = *(const float2*)(in0 + (size_t)(mrow + 8) * MD + n);
                v0.x = fmaf(dp.x, u0.x, v0.x); v0.y = fmaf(dp.y, u0.y, v0.y);
                v1.x = fmaf(dp.x, u1.x, v1.x); v1.y = fmaf(dp.y, u1.y, v1.y);
                *(float2*)(Cout + (size_t)mrow * MD + n)       = v0;
                *(float2*)(Cout + (size_t)(mrow + 8) * MD + n) = v1;
            }
        }
    }
}

// ------- scan phase 1 (read-only, fp16 input): chunk-local scan -> carry ------
__global__ void __launch_bounds__(256)
scan_local_kernel(const float* __restrict__ gamma_log,
                  const float* __restrict__ thetas,
                  const __half* __restrict__ Xh)
{
    const int p = blockIdx.x * 256 + threadIdx.x;
    const int c = blockIdx.y;
    const int h = p >> 4, q = p & 15;

    const float e  = expf(gamma_log[h]);
    const float g  = expf(-e);
    const float th = thetas[(h << 4) + q];
    const float gc = g * cosf(th);
    const float gs = g * sinf(th);

    float a0 = 0.f, a1 = 0.f;
    const __half2* Xp = (const __half2*)Xh;
    const int base = c * CH;
    #pragma unroll 4
    for (int i = 0; i < CH; i++) {
        const size_t idx = (size_t)(base + i) * (MD/2) + p;
        float2 x = __half22float2(Xp[idx]);
        float b0 = gc*a0 - gs*a1 + x.x;
        float b1 = gs*a0 + gc*a1 + x.y;
        a0 = b0; a1 = b1;
    }
    g_carry[p*NC + c] = make_float2(a0, a1);
}

// ---------------- scan phase 2: exclusive scan of chunk carries ---------------
__global__ void __launch_bounds__(256)
scan_carry_kernel(const float* __restrict__ gamma_log,
                  const float* __restrict__ thetas)
{
    const int p = blockIdx.x * 256 + threadIdx.x;
    const int h = p >> 4, q = p & 15;

    const float e   = expf(gamma_log[h]);
    const float gC  = expf(-(float)CH * e);
    const float thC = thetas[(h << 4) + q] * (float)CH;
    const float cs  = cosf(thC), sn = sinf(thC);

    float a0 = 0.f, a1 = 0.f;
    for (int c = 0; c < NC; c++) {
        g_carryExc[p*NC + c] = make_float2(a0, a1);
        float2 l = g_carry[p*NC + c];
        float b0 = gC*(cs*a0 - sn*a1) + l.x;
        float b1 = gC*(sn*a0 + cs*a1) + l.y;
        a0 = b0; a1 = b1;
    }
}

// --- scan phase 3: recompute local scan seeded with carry; write fp16 hidden --
__global__ void __launch_bounds__(256)
scan_apply_half_kernel(const float* __restrict__ gamma_log,
                       const float* __restrict__ thetas,
                       const __half* __restrict__ Xh,
                       __half* __restrict__ Hh)
{
    const int p = blockIdx.x * 256 + threadIdx.x;
    const int c = blockIdx.y;

    const int h = p >> 4, q = p & 15;
    const float e  = expf(gamma_log[h]);
    const float g  = expf(-e);
    const float th = thetas[(h << 4) + q];
    const float gc = g * cosf(th);
    const float gs = g * sinf(th);

    float2 v = g_carryExc[p*NC + c];     // incoming prefix ((0,0) for c==0)
    float v0 = v.x, v1 = v.y;
    const __half2* Xp = (const __half2*)Xh;
    __half2* Hp = (__half2*)Hh;
    const int base = c * CH;
    #pragma unroll 4
    for (int i = 0; i < CH; i++) {
        const size_t idx = (size_t)(base + i) * (MD/2) + p;
        float2 x = __half22float2(Xp[idx]);
        float b0 = gc*v0 - gs*v1 + x.x;
        float b1 = gs*v0 + gc*v1 + x.y;
        v0 = b0; v1 = b1;
        Hp[idx] = __floats2half2_rn(v0, v1);
    }
}

// ---------------- launch ------------------------------------------------------
extern "C" void kernel_launch(void* const* d_in, const int* in_sizes, int n_in,
                              void* d_out, int out_size)
{
    const float* in_seq    = (const float*)d_in[0];   // (8192, 2048)
    const float* thetas    = (const float*)d_in[1];   // (64, 16)
    const float* Mmat      = (const float*)d_in[2];   // (64, 32, 32)
    const float* Bmat      = (const float*)d_in[3];   // (64, 32, 2048)
    const float* Cmat      = (const float*)d_in[4];   // (2048, 2048)
    const float* Dvec      = (const float*)d_in[5];   // (2048,)
    const float* gamma_log = (const float*)d_in[6];   // (64, 1)
    float* out = (float*)d_out;                       // (8192, 2048)

    cudaFuncSetAttribute(mma_gemm_kernel<0>, cudaFuncAttributeMaxDynamicSharedMemorySize, GEMM_SMEM);
    cudaFuncSetAttribute(mma_gemm_kernel<1>, cudaFuncAttributeMaxDynamicSharedMemorySize, GEMM_SMEM);

    __half *pAh, *pXh, *pW1h, *pCh;
    cudaGetSymbolAddress((void**)&pAh,  g_Ah);
    cudaGetSymbolAddress((void**)&pXh,  g_Xh);
    cudaGetSymbolAddress((void**)&pW1h, g_W1h);
    cudaGetSymbolAddress((void**)&pCh,  g_Ch);

    // Launch order: the 4th launch is the one ncu captures -> GEMM0.
    prep_head_kernel<<<NH, 1024>>>(Mmat, Bmat, gamma_log);                          // 1
    beff_split_kernel<<<dim3(MD/256, NH), 256>>>(Bmat);                             // 2
    conv_half_kernel<<<(TSEQ*MD/4 + 255)/256, 256>>>(in_seq, pAh, TSEQ*MD/4);       // 3

    // GEMM0: Xh = U * W1^T (fp16 out)                                              // 4 (profiled)
    mma_gemm_kernel<0><<<dim3(MD/CTA_N, TSEQ/CTA_M), NTHREADS, GEMM_SMEM>>>(
        pAh, pW1h, nullptr, nullptr, nullptr, pXh);

    ceff_split_kernel<<<dim3(MD/256, NH), 256>>>(Cmat);                             // 5

    // scan: phase1 carries (fp16 in), phase2 carry scan, phase3 recompute+fp16
    scan_local_kernel<<<dim3(PAIRS/256, NC), 256>>>(gamma_log, thetas, pXh);        // 6
    scan_carry_kernel<<<PAIRS/256, 256>>>(gamma_log, thetas);                       // 7
    scan_apply_half_kernel<<<dim3(PAIRS/256, NC), 256>>>(gamma_log, thetas, pXh, pAh); // 8

    // GEMM1: out = H * Ceff^T + D .* U
    mma_gemm_kernel<1><<<dim3(MD/CTA_N, TSEQ/CTA_M), NTHREADS, GEMM_SMEM>>>(
        pAh, pCh, in_seq, Dvec, out, nullptr);                                      // 9
}